// round 13
// baseline (speedup 1.0000x reference)
#include <cuda_runtime.h>
#include <cuda_bf16.h>
#include <cstdint>

#define B_ 2
#define H_ 12
#define S_ 256
#define E_ 64
#define D_ 768
#define L_ 25
#define RS (S_ * D_)      // rel sq-stride (floats)
#define CH16 48           // k16 chunks per tile
#define NTILE 512
#define GRID 148
#define RSTR 20           // raw row stride (floats)
#define RBUF (16 * RSTR)  // floats per raw buffer (320)
#define NBUF 6
#define TPB 512
#define NPAD 26
#define WCHUNK (2 * NPAD * 8)   // u32 per k16 chunk (416)
#define WPN 19968               // 96 ksteps x 26 x 8

typedef unsigned long long u64;
typedef unsigned int u32;

// ---- smem layout (float-slot offsets) ----
#define OFF_WS   0              // 19968 u32 (78KB)
#define OFF_RAW  19968          // 16 warps x 6 bufs x 320 = 30720
#define SMEM_FLOATS 50688       // 202752 bytes

__device__ float g_pt[B_ * H_ * S_ * S_];
__device__ u32   g_wp[WPN];
__device__ float g_cv[NTILE * 300];

__device__ __forceinline__ u32 f2tf32(float x) {
    u32 r;
    asm("cvt.rna.tf32.f32 %0, %1;" : "=r"(r) : "f"(x));
    return r;
}

// z<24: transpose p; z==24: pack W k-major NPAD=26 (R10 layout)
__global__ void prep_kernel(const float* __restrict__ p, const float* __restrict__ W) {
    if (blockIdx.z == 24) {
        int flat = blockIdx.y * 8 + blockIdx.x;
        int t = flat * 256 + threadIdx.y * 32 + threadIdx.x;
        if (t >= 96 * NPAD * 4) return;
        int S = t / (NPAD * 4);
        int r = t - S * (NPAD * 4);
        int n = r >> 2, tg = r & 3;
#pragma unroll
        for (int j = 0; j < 2; ++j) {
            int k = 8 * S + tg + 4 * j;
            float wv = (n < L_) ? W[n * D_ + k] : 0.0f;
            g_wp[(S * NPAD + n) * 8 + tg * 2 + j] = f2tf32(wv);
        }
        return;
    }
    __shared__ float tile[32][33];
    int bh = blockIdx.z, x0 = blockIdx.x * 32, y0 = blockIdx.y * 32;
    int tx = threadIdx.x, ty = threadIdx.y;
    const float* src = p + (size_t)bh * (S_ * S_);
#pragma unroll
    for (int j = 0; j < 32; j += 8)
        tile[ty + j][tx] = src[(size_t)(y0 + ty + j) * S_ + (x0 + tx)];
    __syncthreads();
    float* dst = g_pt + (size_t)bh * (S_ * S_);
#pragma unroll
    for (int j = 0; j < 32; j += 8)
        dst[(size_t)(x0 + ty + j) * S_ + (y0 + tx)] = tile[tx][ty + j];
}

// cv[t][l*12+h] = sum_e W[l,64h+e] * v[b,h,sk,e]
__global__ void cv_kernel(const float* __restrict__ v, const float* __restrict__ W) {
    int t = blockIdx.x;
    int lh = threadIdx.x;
    if (lh >= 300) return;
    int l = lh / 12, h = lh - l * 12;
    int b = t >> 8, sk = t & 255;
    const float4* wr = (const float4*)(W + l * D_ + h * 64);
    const float4* vr = (const float4*)(v + (((size_t)b * H_ + h) * S_ + sk) * E_);
    float s = 0.f;
#pragma unroll
    for (int e = 0; e < 16; ++e) {
        float4 a = wr[e], c = vr[e];
        s += a.x * c.x + a.y * c.y + a.z * c.z + a.w * c.w;
    }
    g_cv[t * 300 + lh] = s;
}

__device__ __forceinline__ void cpasync16(u32 dst, const float* src) {
    asm volatile("cp.async.cg.shared.global [%0], [%1], 16;\n" :: "r"(dst), "l"(src));
}
__device__ __forceinline__ void cp_commit() {
    asm volatile("cp.async.commit_group;\n" ::: "memory");
}
__device__ __forceinline__ void cp_wait5() {
    asm volatile("cp.async.wait_group 5;\n" ::: "memory");
}
__device__ __forceinline__ u32 smem_u32(const void* p) {
    u32 r;
    asm("{ .reg .u64 t; cvta.to.shared.u64 t, %1; cvt.u32.u64 %0, t; }" : "=r"(r) : "l"(p));
    return r;
}
__device__ __forceinline__ void mma_tf32(float* c, const u32* a, u32 b0, u32 b1) {
    asm volatile(
        "mma.sync.aligned.m16n8k8.row.col.f32.tf32.tf32.f32 "
        "{%0,%1,%2,%3}, {%4,%5,%6,%7}, {%8,%9}, {%0,%1,%2,%3};"
        : "+f"(c[0]), "+f"(c[1]), "+f"(c[2]), "+f"(c[3])
        : "r"(a[0]), "r"(a[1]), "r"(a[2]), "r"(a[3]), "r"(b0), "r"(b1));
}

__global__ void __launch_bounds__(TPB, 1) mhs_mma_kernel(
    const float* __restrict__ rel,   // [B,S,S,768]
    const float* __restrict__ bias,  // [25]
    float* __restrict__ out)         // [B,S,25,S]
{
    extern __shared__ float smem[];
    const int tid  = threadIdx.x;
    const int w    = tid >> 5;
    const int lane = tid & 31;
    const int g    = lane >> 2;
    const int tg   = lane & 3;

    float* rawb = smem + OFF_RAW + w * (NBUF * RBUF);
    const u32 raw_su = smem_u32(rawb);
    const u32* ws = (const u32*)smem;

    // W frag offsets, n clamped (row 25 zeros)
    int n_off[4];
#pragma unroll
    for (int nt = 0; nt < 4; ++nt) {
        int n = nt * 8 + g;
        if (n > 25) n = 25;
        n_off[nt] = n * 8 + tg * 2;
    }

    // cp.async lane mapping: 2 instrs/chunk (rows g, g+8), 16B per lane
    const size_t loff0 = (size_t)(16 * w + g) * RS + tg * 4;
    const size_t loff1 = (size_t)(16 * w + g + 8) * RS + tg * 4;
    const u32 dst0 = raw_su + (u32)(g * RSTR * 4 + tg * 16);
    const u32 dst1 = dst0 + (u32)(8 * RSTR * 4);

#define TILE_BASE(t) (rel + (size_t)((t) >> 8) * S_ * RS + (size_t)((t) & 255) * D_)
#define ISSUE(base, cc, buf)                                              \
    do {                                                                  \
        const u32 boff = (u32)((buf) * RBUF * 4);                         \
        cpasync16(dst0 + boff, (base) + loff0 + 16 * (cc));               \
        cpasync16(dst1 + boff, (base) + loff1 + 16 * (cc));               \
    } while (0)

    // ---- initial prefetch: tile0 chunks 0..4 into bufs 0..4 ----
    {
        const float* tb = TILE_BASE(blockIdx.x);
#pragma unroll
        for (int c = 0; c < 5; ++c) { ISSUE(tb, c, c); cp_commit(); }
    }

    // ---- stage packed W once (78KB from L2) ----
    {
        const uint4* src = (const uint4*)g_wp;
        uint4* dst = (uint4*)smem;
        for (int i = tid; i < WPN / 4; i += TPB) dst[i] = src[i];
    }
    __syncthreads();   // only block barrier

    // ---- persistent tile loop ----
    for (int t = blockIdx.x; t < NTILE; t += GRID) {
        const int b  = t >> 8;
        const int sk = t & 255;
        const float* tbase = TILE_BASE(t);
        const bool has_next = (t + GRID < NTILE);
        const float* tbase2 = has_next ? TILE_BASE(t + GRID) : tbase;

        const float* ptb = g_pt + ((size_t)b * H_) * (S_ * S_) + sk * S_ + 16 * w;
        float pvA = __ldg(ptb + g);
        float pvB = __ldg(ptb + g + 8);
        float pvAn = pvA, pvBn = pvB;

        float acc[4][4];
#pragma unroll
        for (int nt = 0; nt < 4; ++nt)
#pragma unroll
            for (int q = 0; q < 4; ++q) acc[nt][q] = 0.f;

#pragma unroll 1
        for (int c0 = 0; c0 < CH16; c0 += 12) {
            const u32* wb = ws + c0 * WCHUNK;
#pragma unroll
            for (int u = 0; u < 12; ++u) {
                const int cc = c0 + u;

                // issue chunk cc+5 into buf (u+5)%6
                {
                    const int c5 = cc + 5;
                    if (c5 < CH16) {
                        ISSUE(tbase, c5, (u + 5) % 6);
                    } else if (has_next) {
                        ISSUE(tbase2, c5 - CH16, (u + 5) % 6);
                    }
                }
                cp_commit();
                cp_wait5();        // chunk cc resident

                // pv prefetch for next h (static positions)
                if (u == 1 || u == 5 || u == 9) {
                    int hn = (cc + 3) >> 2;
                    if (hn > H_ - 1) hn = H_ - 1;
                    pvAn = __ldg(ptb + (size_t)hn * (S_ * S_) + g);
                    pvBn = __ldg(ptb + (size_t)hn * (S_ * S_) + g + 8);
                }

                // convert chunk cc (buf u%6): y = pv * rel -> tf32 frags
                u32 a[2][4];
                {
                    const float* rp = rawb + (u % 6) * RBUF;
                    const float* q0 = rp + g * RSTR + tg;
                    const float* q1 = rp + (g + 8) * RSTR + tg;
#pragma unroll
                    for (int s = 0; s < 2; ++s) {
                        a[s][0] = f2tf32(q0[8 * s] * pvA);
                        a[s][1] = f2tf32(q1[8 * s] * pvB);
                        a[s][2] = f2tf32(q0[8 * s + 4] * pvA);
                        a[s][3] = f2tf32(q1[8 * s + 4] * pvB);
                    }
                }

                // MMAs: 4 ntiles x 2 ksteps
#pragma unroll
                for (int nt = 0; nt < 4; ++nt) {
#pragma unroll
                    for (int s = 0; s < 2; ++s) {
                        u64 bp = *(const u64*)(wb + u * WCHUNK + s * (NPAD * 8) + n_off[nt]);
                        u32 b0 = (u32)bp, b1 = (u32)(bp >> 32);
                        mma_tf32(acc[nt], a[s], b0, b1);
                    }
                }

                // h-boundary pv swap (static positions)
                if (u == 3 || u == 7 || u == 11) { pvA = pvAn; pvB = pvBn; }
            }
        }

        // ---- per-warp epilogue ----
        const float* pte = g_pt + ((size_t)b * H_) * (S_ * S_) + sk * S_;
        const float* cvp = g_cv + (size_t)t * 300;
        float* ob = out + ((size_t)t * L_) * S_;
#pragma unroll
        for (int i = 0; i < 2; ++i) {
            const int row = 16 * w + g + 8 * i;
            float pr[H_];
#pragma unroll
            for (int h = 0; h < H_; ++h)
                pr[h] = __ldg(pte + (size_t)h * (S_ * S_) + row);
#pragma unroll
            for (int nt = 0; nt < 4; ++nt) {
#pragma unroll
                for (int j = 0; j < 2; ++j) {
                    const int l = 8 * nt + 2 * tg + j;
                    if (l < L_) {
                        float val = acc[nt][2 * i + j] + __ldg(bias + l);
#pragma unroll
                        for (int h = 0; h < H_; ++h)
                            val += pr[h] * __ldg(cvp + l * H_ + h);
                        ob[(size_t)l * S_ + row] = val;
                    }
                }
            }
        }
    }
#undef ISSUE
#undef TILE_BASE
}

extern "C" void kernel_launch(void* const* d_in, const int* in_sizes, int n_in,
                              void* d_out, int out_size) {
    const float* p    = (const float*)d_in[0];
    const float* v    = (const float*)d_in[1];
    const float* rel  = (const float*)d_in[2];
    const float* W    = (const float*)d_in[3];
    const float* bias = (const float*)d_in[4];
    float* out = (float*)d_out;

    dim3 gt(S_ / 32, S_ / 32, B_ * H_ + 1);
    prep_kernel<<<gt, dim3(32, 8)>>>(p, W);
    cv_kernel<<<NTILE, 320>>>(v, W);

    const int smem_bytes = SMEM_FLOATS * (int)sizeof(float);  // 202752
    cudaFuncSetAttribute(mhs_mma_kernel,
                         cudaFuncAttributeMaxDynamicSharedMemorySize, smem_bytes);
    mhs_mma_kernel<<<GRID, TPB, smem_bytes>>>(rel, bias, out);
}